// round 11
// baseline (speedup 1.0000x reference)
#include <cuda_runtime.h>
#include <cstdint>

// ---------------------------------------------------------------------------
#define M_MODES 10
#define N_PHOT  5
#define N_NB    252     // C(10,5)
#define N_B     2002    // C(14,5)

// ---------------------------------------------------------------------------
// Compile-time Fock tables (input-independent): packed rows + 1/norm.
// ---------------------------------------------------------------------------
struct Tables {
    unsigned nb[N_NB];
    unsigned bb[N_B];
    float    inv_norm[N_B];
};

constexpr unsigned pack5(int a, int b, int c, int d, int e) {
    return (unsigned)a | ((unsigned)b << 4) | ((unsigned)c << 8) |
           ((unsigned)d << 12) | ((unsigned)e << 16);
}

constexpr Tables make_tables() {
    Tables T{};
    int i = 0;
    for (int a = 0; a < 10; a++)
        for (int b = a + 1; b < 10; b++)
            for (int c = b + 1; c < 10; c++)
                for (int d = c + 1; d < 10; d++)
                    for (int e = d + 1; e < 10; e++)
                        T.nb[i++] = pack5(a, b, c, d, e);
    i = 0;
    for (int a = 0; a < 10; a++)
        for (int b = a; b < 10; b++)
            for (int c = b; c < 10; c++)
                for (int d = c; d < 10; d++)
                    for (int e = d; e < 10; e++) {
                        T.bb[i] = pack5(a, b, c, d, e);
                        int cnt[10] = {};
                        cnt[a]++; cnt[b]++; cnt[c]++; cnt[d]++; cnt[e]++;
                        float fact[6] = {1.f, 1.f, 2.f, 6.f, 24.f, 120.f};
                        float norm = 1.f;
                        for (int m = 0; m < 10; m++) norm *= fact[cnt[m]];
                        T.inv_norm[i] = 1.0f / norm;
                        i++;
                    }
    return T;
}

__device__ constexpr Tables g_tab = make_tables();

// ---------------------------------------------------------------------------
__device__ __forceinline__ float2 cmul(float2 a, float2 b) {
    return make_float2(fmaf(a.x, b.x, -a.y * b.y), fmaf(a.x, b.y, a.y * b.x));
}
__device__ __forceinline__ float2 cadd(float2 a, float2 b) {
    return make_float2(a.x + b.x, a.y + b.y);
}

// ---------------------------------------------------------------------------
// Glynn |perm|^2, single matrix (known-good codegen from the 17.3us kernel).
// ---------------------------------------------------------------------------
__device__ __forceinline__ float perm_prob(const float2 (*__restrict__ V)[5], unsigned packed) {
    float2 M[5][5];
    #pragma unroll
    for (int i = 0; i < 5; i++) {
        int ri = (packed >> (4 * i)) & 15;
        #pragma unroll
        for (int j = 0; j < 5; j++) M[i][j] = V[ri][j];
    }
    float2 rs[5];
    #pragma unroll
    for (int j = 0; j < 5; j++) {
        rs[j].x = M[0][j].x + M[1][j].x + M[2][j].x + M[3][j].x + M[4][j].x;
        rs[j].y = M[0][j].y + M[1][j].y + M[2][j].y + M[3][j].y + M[4][j].y;
    }
    float sx = 0.f, sy = 0.f;
    #pragma unroll
    for (int g = 0; g < 16; g++) {
        float2 p01 = cmul(rs[0], rs[1]);
        float2 p23 = cmul(rs[2], rs[3]);
        float2 p = cmul(cmul(p01, p23), rs[4]);
        if (g & 1) { sx -= p.x; sy -= p.y; }
        else       { sx += p.x; sy += p.y; }
        if (g < 15) {
            int gc = g ^ (g >> 1);
            int gn = (g + 1) ^ ((g + 1) >> 1);
            int diff = gc ^ gn;
            int i = __ffs(diff);   // 1..4, compile-time after unroll
            float dlt = (gn & diff) ? -2.f : 2.f;
            #pragma unroll
            for (int j = 0; j < 5; j++) {
                rs[j].x = fmaf(dlt, M[i][j].x, rs[j].x);
                rs[j].y = fmaf(dlt, M[i][j].y, rs[j].y);
            }
        }
    }
    sx *= 0.0625f;
    sy *= 0.0625f;
    return fmaf(sx, sx, sy * sy);
}

// ---------------------------------------------------------------------------
// Dual Glynn |perm|^2: two independent permanents interleaved for ILP.
// (known-good codegen from the 17.3us kernel)
// ---------------------------------------------------------------------------
__device__ __forceinline__ void perm_prob_dual(const float2 (*__restrict__ V)[5],
                                               unsigned pa, unsigned pb,
                                               float& outA, float& outB) {
    int ra0 =  pa        & 15, ra1 = (pa >> 4)  & 15, ra2 = (pa >> 8)  & 15;
    int ra3 = (pa >> 12) & 15, ra4 = (pa >> 16) & 15;
    int rb0 =  pb        & 15, rb1 = (pb >> 4)  & 15, rb2 = (pb >> 8)  & 15;
    int rb3 = (pb >> 12) & 15, rb4 = (pb >> 16) & 15;

    float2 MA1[5], MA2[5], MB1[5], MB2[5];
    float2 rsA[5], rsB[5];
    #pragma unroll
    for (int j = 0; j < 5; j++) {
        float2 a1 = V[ra1][j], a2 = V[ra2][j];
        MA1[j] = a1; MA2[j] = a2;
        float2 a0 = V[ra0][j], a3 = V[ra3][j], a4 = V[ra4][j];
        rsA[j].x = a0.x + a1.x + a2.x + a3.x + a4.x;
        rsA[j].y = a0.y + a1.y + a2.y + a3.y + a4.y;
        float2 b1 = V[rb1][j], b2 = V[rb2][j];
        MB1[j] = b1; MB2[j] = b2;
        float2 b0 = V[rb0][j], b3 = V[rb3][j], b4 = V[rb4][j];
        rsB[j].x = b0.x + b1.x + b2.x + b3.x + b4.x;
        rsB[j].y = b0.y + b1.y + b2.y + b3.y + b4.y;
    }

    float sxA = 0.f, syA = 0.f, sxB = 0.f, syB = 0.f;
    #pragma unroll
    for (int g = 0; g < 16; g++) {
        {
            float2 p01 = cmul(rsA[0], rsA[1]);
            float2 p23 = cmul(rsA[2], rsA[3]);
            float2 p = cmul(cmul(p01, p23), rsA[4]);
            if (g & 1) { sxA -= p.x; syA -= p.y; }
            else       { sxA += p.x; syA += p.y; }
        }
        {
            float2 p01 = cmul(rsB[0], rsB[1]);
            float2 p23 = cmul(rsB[2], rsB[3]);
            float2 p = cmul(cmul(p01, p23), rsB[4]);
            if (g & 1) { sxB -= p.x; syB -= p.y; }
            else       { sxB += p.x; syB += p.y; }
        }
        if (g < 15) {
            int gc = g ^ (g >> 1);
            int gn = (g + 1) ^ ((g + 1) >> 1);
            int diff = gc ^ gn;
            int r = __ffs(diff);                       // 1..4, compile-time
            float dlt = (gn & diff) ? -2.f : 2.f;
            #pragma unroll
            for (int j = 0; j < 5; j++) {
                float2 ma, mb;
                if (r == 1)      { ma = MA1[j];     mb = MB1[j]; }
                else if (r == 2) { ma = MA2[j];     mb = MB2[j]; }
                else if (r == 3) { ma = V[ra3][j];  mb = V[rb3][j]; }
                else             { ma = V[ra4][j];  mb = V[rb4][j]; }
                rsA[j].x = fmaf(dlt, ma.x, rsA[j].x);
                rsA[j].y = fmaf(dlt, ma.y, rsA[j].y);
                rsB[j].x = fmaf(dlt, mb.x, rsB[j].x);
                rsB[j].y = fmaf(dlt, mb.y, rsB[j].y);
            }
        }
    }
    sxA *= 0.0625f; syA *= 0.0625f;
    sxB *= 0.0625f; syB *= 0.0625f;
    outA = fmaf(sxA, sxA, syA * syA);
    outB = fmaf(sxB, sxB, syB * syB);
}

// ---------------------------------------------------------------------------
// Single fused kernel: one block per batch element, 512 threads.
// ---------------------------------------------------------------------------
__global__ __launch_bounds__(512, 1)
void qc_main(const float* __restrict__ x, const float* __restrict__ Wd,
             const float* __restrict__ bd,
             const float* __restrict__ ph_l1, const float* __restrict__ ph_r1,
             const float* __restrict__ ph_lf, const float* __restrict__ ph_rf,
             const float* __restrict__ Wo, const float* __restrict__ bo,
             float* __restrict__ out) {
    int b = blockIdx.x;
    int t = threadIdx.x;
    int lane = t & 31;
    int w = t >> 5;   // 16 warps

    __shared__ float2 sh_T[4][45][4];
    __shared__ float2 sh_WR1[10][10];
    __shared__ float2 sh_WL1c[10][5];
    __shared__ float2 sh_WRF[10][10];
    __shared__ float2 sh_WLFc[10][5];
    __shared__ float2 sh_eih[10];
    __shared__ float2 sh_V[10][5];
    __shared__ float  sh_e1[N_NB];
    __shared__ float  sh_red[16][10];

    if (t >= 320) {
        // ---- interferometer build on warps 10-15 (192 threads) ----
        int l = t - 320;
        if (l < 180) {
            int g = l / 45, k = l % 45;
            const float* ph = (g == 0) ? ph_l1 : (g == 1) ? ph_r1 : (g == 2) ? ph_lf : ph_rf;
            float t1 = ph[2 * k], t2 = ph[2 * k + 1];
            float s1, c1, s2, c2v;
            sincosf(t1, &s1, &c1);
            sincosf(t2, &s2, &c2v);
            float2 e1 = make_float2(c1, s1), e2 = make_float2(c2v, s2);
            const float s = 0.7071067811865476f;
            float2 B00 = make_float2(s, 0), B01 = make_float2(0, s);
            float2 B10 = make_float2(0, s), B11 = make_float2(s, 0);
            float2 M100 = cmul(e1, B00), M101 = cmul(e1, B01);
            float2 M110 = B10, M111 = B11;
            float2 M200 = cadd(cmul(B00, M100), cmul(B01, M110));
            float2 M201 = cadd(cmul(B00, M101), cmul(B01, M111));
            float2 M210 = cadd(cmul(B10, M100), cmul(B11, M110));
            float2 M211 = cadd(cmul(B10, M101), cmul(B11, M111));
            sh_T[g][k][0] = cmul(e2, M200);
            sh_T[g][k][1] = cmul(e2, M201);
            sh_T[g][k][2] = M210;
            sh_T[g][k][3] = M211;
        }
        asm volatile("bar.sync 1, 192;" ::: "memory");
        if (l < 40) {
            int g = l / 10, col = l % 10;
            float2 u[10];
            #pragma unroll
            for (int m = 0; m < 10; m++) u[m] = make_float2(m == col ? 1.f : 0.f, 0.f);
            int k = 0;
            for (int layer = 0; layer < 10; layer++) {
                for (int p = (layer & 1); p < 9; p += 2) {
                    float2 a = u[p], bb2 = u[p + 1];
                    u[p]     = cadd(cmul(sh_T[g][k][0], a), cmul(sh_T[g][k][1], bb2));
                    u[p + 1] = cadd(cmul(sh_T[g][k][2], a), cmul(sh_T[g][k][3], bb2));
                    k++;
                }
            }
            if (g == 0) {
                if ((col & 1) == 0)
                    for (int m = 0; m < 10; m++) sh_WL1c[m][col >> 1] = u[m];
            } else if (g == 1) {
                for (int m = 0; m < 10; m++) sh_WR1[m][col] = u[m];
            } else if (g == 2) {
                if ((col & 1) == 0)
                    for (int m = 0; m < 10; m++) sh_WLFc[m][col >> 1] = u[m];
            } else {
                for (int m = 0; m < 10; m++) sh_WRF[m][col] = u[m];
            }
        }
    } else if (w < 10) {
        // ---- projection: h = (x@Wd + bd)/pi, warp w -> mode w ----
        float acc = 0.f;
        const float* xb = x + b * 784;
        for (int i = lane; i < 784; i += 32) acc = fmaf(xb[i], Wd[i * 10 + w], acc);
        #pragma unroll
        for (int o = 16; o; o >>= 1) acc += __shfl_xor_sync(0xffffffffu, acc, o);
        if (lane == 0) {
            float h = (acc + bd[w]) * 0.3183098861837907f;  // 1/pi
            float sn, cs;
            sincosf(h, &sn, &cs);
            sh_eih[w] = make_float2(cs, sn);
        }
    }
    __syncthreads();

    // 2. V1[m][j] = sum_k WR1[m][k] * e^{ih_k} * WL1c[k][j]
    if (t < 50) {
        int m = t / 5, j = t % 5;
        float2 v = make_float2(0.f, 0.f);
        #pragma unroll
        for (int k = 0; k < 10; k++)
            v = cadd(v, cmul(sh_WR1[m][k], cmul(sh_eih[k], sh_WL1c[k][j])));
        sh_V[m][j] = v;
    }
    __syncthreads();

    // 3. 252 no-bunching probabilities, 2-way ILP (126 threads x dual)
    if (t < 126) {
        float pA, pB;
        perm_prob_dual(sh_V, g_tab.nb[t], g_tab.nb[t + 126], pA, pB);
        sh_e1[t] = pA;
        sh_e1[t + 126] = pB;
    }
    __syncthreads();

    // 4. phi2[m] = sum_j e1[m + 10j]; then e^{i phi2}
    if (t < 10) {
        float phi = 0.f;
        for (int j2 = t; j2 < N_NB; j2 += 10) phi += sh_e1[j2];
        float sn, cs;
        sincosf(phi, &sn, &cs);
        sh_eih[t] = make_float2(cs, sn);
    }
    __syncthreads();

    // 5. VF[m][j]
    if (t < 50) {
        int m = t / 5, j = t % 5;
        float2 v = make_float2(0.f, 0.f);
        #pragma unroll
        for (int k = 0; k < 10; k++)
            v = cadd(v, cmul(sh_WRF[m][k], cmul(sh_eih[k], sh_WLFc[k][j])));
        sh_V[m][j] = v;
    }
    __syncthreads();

    // 6. 2002 bunched perms, 2-way ILP, uniform workload (clamped + 0-weight),
    //    fused with probs @ W_out
    float acc[10];
    #pragma unroll
    for (int c = 0; c < 10; c++) acc[c] = 0.f;

    #pragma unroll
    for (int pass = 0; pass < 2; pass++) {
        int kA = t + pass * 1024;          // max 1535 < 2002, always valid
        int kB = kA + 512;                  // may exceed for pass 1
        int kBc = (kB < N_B) ? kB : (N_B - 1);
        float wB = (kB < N_B) ? g_tab.inv_norm[kB] : 0.f;
        float pA, pB;
        perm_prob_dual(sh_V, g_tab.bb[kA], g_tab.bb[kBc], pA, pB);
        pA *= g_tab.inv_norm[kA];
        pB *= wB;
        const float* wa = Wo + kA * 10;
        const float* wb = Wo + kBc * 10;
        #pragma unroll
        for (int c = 0; c < 10; c++) {
            acc[c] = fmaf(pA, wa[c], acc[c]);
            acc[c] = fmaf(pB, wb[c], acc[c]);
        }
    }

    #pragma unroll
    for (int c = 0; c < 10; c++) {
        #pragma unroll
        for (int o = 16; o; o >>= 1) acc[c] += __shfl_xor_sync(0xffffffffu, acc[c], o);
    }
    if (lane == 0) {
        #pragma unroll
        for (int c = 0; c < 10; c++) sh_red[w][c] = acc[c];
    }
    __syncthreads();
    if (t < 10) {
        float v = bo[t];
        #pragma unroll
        for (int ww = 0; ww < 16; ww++) v += sh_red[ww][t];
        out[b * 10 + t] = v;
    }
}

// ---------------------------------------------------------------------------
extern "C" void kernel_launch(void* const* d_in, const int* in_sizes, int n_in,
                              void* d_out, int out_size) {
    const float* x   = (const float*)d_in[0];
    const float* Wd  = (const float*)d_in[1];
    const float* bd  = (const float*)d_in[2];
    const float* pl1 = (const float*)d_in[3];
    const float* pr1 = (const float*)d_in[4];
    const float* plf = (const float*)d_in[5];
    const float* prf = (const float*)d_in[6];
    const float* Wo  = (const float*)d_in[7];
    const float* bo  = (const float*)d_in[8];
    float* out = (float*)d_out;

    int B = in_sizes[0] / 784;

    qc_main<<<B, 512>>>(x, Wd, bd, pl1, pr1, plf, prf, Wo, bo, out);
}

// round 15
// speedup vs baseline: 1.4583x; 1.4583x over previous
#include <cuda_runtime.h>
#include <cstdint>

// ---------------------------------------------------------------------------
#define M_MODES 10
#define N_PHOT  5
#define N_NB    252     // C(10,5)
#define N_B     2002    // C(14,5)

// ---------------------------------------------------------------------------
// Compile-time Fock tables (input-independent): packed rows + 1/norm.
// ---------------------------------------------------------------------------
struct Tables {
    unsigned nb[N_NB];
    unsigned bb[N_B];
    float    inv_norm[N_B];
};

constexpr unsigned pack5(int a, int b, int c, int d, int e) {
    return (unsigned)a | ((unsigned)b << 4) | ((unsigned)c << 8) |
           ((unsigned)d << 12) | ((unsigned)e << 16);
}

constexpr Tables make_tables() {
    Tables T{};
    int i = 0;
    for (int a = 0; a < 10; a++)
        for (int b = a + 1; b < 10; b++)
            for (int c = b + 1; c < 10; c++)
                for (int d = c + 1; d < 10; d++)
                    for (int e = d + 1; e < 10; e++)
                        T.nb[i++] = pack5(a, b, c, d, e);
    i = 0;
    for (int a = 0; a < 10; a++)
        for (int b = a; b < 10; b++)
            for (int c = b; c < 10; c++)
                for (int d = c; d < 10; d++)
                    for (int e = d; e < 10; e++) {
                        T.bb[i] = pack5(a, b, c, d, e);
                        int cnt[10] = {};
                        cnt[a]++; cnt[b]++; cnt[c]++; cnt[d]++; cnt[e]++;
                        float fact[6] = {1.f, 1.f, 2.f, 6.f, 24.f, 120.f};
                        float norm = 1.f;
                        for (int m = 0; m < 10; m++) norm *= fact[cnt[m]];
                        T.inv_norm[i] = 1.0f / norm;
                        i++;
                    }
    return T;
}

__device__ constexpr Tables g_tab = make_tables();

// ---------------------------------------------------------------------------
__device__ __forceinline__ float2 cmul(float2 a, float2 b) {
    return make_float2(fmaf(a.x, b.x, -a.y * b.y), fmaf(a.x, b.y, a.y * b.x));
}
__device__ __forceinline__ float2 cadd(float2 a, float2 b) {
    return make_float2(a.x + b.x, a.y + b.y);
}

// ---------------------------------------------------------------------------
// Glynn |perm|^2, single matrix (known-good codegen).
// V rows padded to 6 float2 (48B, 16B-aligned) for vectorized LDS.
// ---------------------------------------------------------------------------
__device__ __forceinline__ float perm_prob(const float2 (*__restrict__ V)[6], unsigned packed) {
    float2 M[5][5];
    #pragma unroll
    for (int i = 0; i < 5; i++) {
        int ri = (packed >> (4 * i)) & 15;
        #pragma unroll
        for (int j = 0; j < 5; j++) M[i][j] = V[ri][j];
    }
    float2 rs[5];
    #pragma unroll
    for (int j = 0; j < 5; j++) {
        rs[j].x = M[0][j].x + M[1][j].x + M[2][j].x + M[3][j].x + M[4][j].x;
        rs[j].y = M[0][j].y + M[1][j].y + M[2][j].y + M[3][j].y + M[4][j].y;
    }
    float sx = 0.f, sy = 0.f;
    #pragma unroll
    for (int g = 0; g < 16; g++) {
        float2 p01 = cmul(rs[0], rs[1]);
        float2 p23 = cmul(rs[2], rs[3]);
        float2 p = cmul(cmul(p01, p23), rs[4]);
        if (g & 1) { sx -= p.x; sy -= p.y; }
        else       { sx += p.x; sy += p.y; }
        if (g < 15) {
            int gc = g ^ (g >> 1);
            int gn = (g + 1) ^ ((g + 1) >> 1);
            int diff = gc ^ gn;
            int i = __ffs(diff);   // 1..4, compile-time after unroll
            float dlt = (gn & diff) ? -2.f : 2.f;
            #pragma unroll
            for (int j = 0; j < 5; j++) {
                rs[j].x = fmaf(dlt, M[i][j].x, rs[j].x);
                rs[j].y = fmaf(dlt, M[i][j].y, rs[j].y);
            }
        }
    }
    sx *= 0.0625f;
    sy *= 0.0625f;
    return fmaf(sx, sx, sy * sy);
}

// ---------------------------------------------------------------------------
// Dual Glynn |perm|^2: two independent permanents interleaved for ILP.
// (known-good codegen from the 17.3us kernel; only the V row type changed)
// ---------------------------------------------------------------------------
__device__ __forceinline__ void perm_prob_dual(const float2 (*__restrict__ V)[6],
                                               unsigned pa, unsigned pb,
                                               float& outA, float& outB) {
    int ra0 =  pa        & 15, ra1 = (pa >> 4)  & 15, ra2 = (pa >> 8)  & 15;
    int ra3 = (pa >> 12) & 15, ra4 = (pa >> 16) & 15;
    int rb0 =  pb        & 15, rb1 = (pb >> 4)  & 15, rb2 = (pb >> 8)  & 15;
    int rb3 = (pb >> 12) & 15, rb4 = (pb >> 16) & 15;

    float2 MA1[5], MA2[5], MB1[5], MB2[5];
    float2 rsA[5], rsB[5];
    #pragma unroll
    for (int j = 0; j < 5; j++) {
        float2 a1 = V[ra1][j], a2 = V[ra2][j];
        MA1[j] = a1; MA2[j] = a2;
        float2 a0 = V[ra0][j], a3 = V[ra3][j], a4 = V[ra4][j];
        rsA[j].x = a0.x + a1.x + a2.x + a3.x + a4.x;
        rsA[j].y = a0.y + a1.y + a2.y + a3.y + a4.y;
        float2 b1 = V[rb1][j], b2 = V[rb2][j];
        MB1[j] = b1; MB2[j] = b2;
        float2 b0 = V[rb0][j], b3 = V[rb3][j], b4 = V[rb4][j];
        rsB[j].x = b0.x + b1.x + b2.x + b3.x + b4.x;
        rsB[j].y = b0.y + b1.y + b2.y + b3.y + b4.y;
    }

    float sxA = 0.f, syA = 0.f, sxB = 0.f, syB = 0.f;
    #pragma unroll
    for (int g = 0; g < 16; g++) {
        {
            float2 p01 = cmul(rsA[0], rsA[1]);
            float2 p23 = cmul(rsA[2], rsA[3]);
            float2 p = cmul(cmul(p01, p23), rsA[4]);
            if (g & 1) { sxA -= p.x; syA -= p.y; }
            else       { sxA += p.x; syA += p.y; }
        }
        {
            float2 p01 = cmul(rsB[0], rsB[1]);
            float2 p23 = cmul(rsB[2], rsB[3]);
            float2 p = cmul(cmul(p01, p23), rsB[4]);
            if (g & 1) { sxB -= p.x; syB -= p.y; }
            else       { sxB += p.x; syB += p.y; }
        }
        if (g < 15) {
            int gc = g ^ (g >> 1);
            int gn = (g + 1) ^ ((g + 1) >> 1);
            int diff = gc ^ gn;
            int r = __ffs(diff);                       // 1..4, compile-time
            float dlt = (gn & diff) ? -2.f : 2.f;
            #pragma unroll
            for (int j = 0; j < 5; j++) {
                float2 ma, mb;
                if (r == 1)      { ma = MA1[j];     mb = MB1[j]; }
                else if (r == 2) { ma = MA2[j];     mb = MB2[j]; }
                else if (r == 3) { ma = V[ra3][j];  mb = V[rb3][j]; }
                else             { ma = V[ra4][j];  mb = V[rb4][j]; }
                rsA[j].x = fmaf(dlt, ma.x, rsA[j].x);
                rsA[j].y = fmaf(dlt, ma.y, rsA[j].y);
                rsB[j].x = fmaf(dlt, mb.x, rsB[j].x);
                rsB[j].y = fmaf(dlt, mb.y, rsB[j].y);
            }
        }
    }
    sxA *= 0.0625f; syA *= 0.0625f;
    sxB *= 0.0625f; syB *= 0.0625f;
    outA = fmaf(sxA, sxA, syA * syA);
    outB = fmaf(sxB, sxB, syB * syB);
}

// ---------------------------------------------------------------------------
// Single fused kernel: one block per batch element, 512 threads.
// ---------------------------------------------------------------------------
__global__ __launch_bounds__(512, 1)
void qc_main(const float* __restrict__ x, const float* __restrict__ Wd,
             const float* __restrict__ bd,
             const float* __restrict__ ph_l1, const float* __restrict__ ph_r1,
             const float* __restrict__ ph_lf, const float* __restrict__ ph_rf,
             const float* __restrict__ Wo, const float* __restrict__ bo,
             float* __restrict__ out) {
    int b = blockIdx.x;
    int t = threadIdx.x;
    int lane = t & 31;
    int w = t >> 5;   // 16 warps

    __shared__ float2 sh_T[4][45][4];
    __shared__ float2 sh_WR1[10][10];
    __shared__ float2 sh_WL1c[10][5];
    __shared__ float2 sh_WRF[10][10];
    __shared__ float2 sh_WLFc[10][5];
    __shared__ float2 sh_eih[10];
    __shared__ float2 sh_V[10][6];      // padded: 48B rows, 16B aligned
    __shared__ float  sh_e1[N_NB];
    __shared__ float  sh_red[16][10];

    if (t >= 320) {
        // ---- interferometer build on warps 10-15 (192 threads) ----
        int l = t - 320;
        if (l < 180) {
            int g = l / 45, k = l % 45;
            const float* ph = (g == 0) ? ph_l1 : (g == 1) ? ph_r1 : (g == 2) ? ph_lf : ph_rf;
            float t1 = ph[2 * k], t2 = ph[2 * k + 1];
            float s1, c1, s2, c2v;
            sincosf(t1, &s1, &c1);
            sincosf(t2, &s2, &c2v);
            float2 e1 = make_float2(c1, s1), e2 = make_float2(c2v, s2);
            const float s = 0.7071067811865476f;
            float2 B00 = make_float2(s, 0), B01 = make_float2(0, s);
            float2 B10 = make_float2(0, s), B11 = make_float2(s, 0);
            float2 M100 = cmul(e1, B00), M101 = cmul(e1, B01);
            float2 M110 = B10, M111 = B11;
            float2 M200 = cadd(cmul(B00, M100), cmul(B01, M110));
            float2 M201 = cadd(cmul(B00, M101), cmul(B01, M111));
            float2 M210 = cadd(cmul(B10, M100), cmul(B11, M110));
            float2 M211 = cadd(cmul(B10, M101), cmul(B11, M111));
            sh_T[g][k][0] = cmul(e2, M200);
            sh_T[g][k][1] = cmul(e2, M201);
            sh_T[g][k][2] = M210;
            sh_T[g][k][3] = M211;
        }
        asm volatile("bar.sync 1, 192;" ::: "memory");
        if (l < 40) {
            int g = l / 10, col = l % 10;
            float2 u[10];
            #pragma unroll
            for (int m = 0; m < 10; m++) u[m] = make_float2(m == col ? 1.f : 0.f, 0.f);
            int k = 0;
            for (int layer = 0; layer < 10; layer++) {
                for (int p = (layer & 1); p < 9; p += 2) {
                    float2 a = u[p], bb2 = u[p + 1];
                    u[p]     = cadd(cmul(sh_T[g][k][0], a), cmul(sh_T[g][k][1], bb2));
                    u[p + 1] = cadd(cmul(sh_T[g][k][2], a), cmul(sh_T[g][k][3], bb2));
                    k++;
                }
            }
            if (g == 0) {
                if ((col & 1) == 0)
                    for (int m = 0; m < 10; m++) sh_WL1c[m][col >> 1] = u[m];
            } else if (g == 1) {
                for (int m = 0; m < 10; m++) sh_WR1[m][col] = u[m];
            } else if (g == 2) {
                if ((col & 1) == 0)
                    for (int m = 0; m < 10; m++) sh_WLFc[m][col >> 1] = u[m];
            } else {
                for (int m = 0; m < 10; m++) sh_WRF[m][col] = u[m];
            }
        }
    } else if (w < 10) {
        // ---- projection: h = (x@Wd + bd)/pi, warp w -> mode w ----
        float acc = 0.f;
        const float* xb = x + b * 784;
        for (int i = lane; i < 784; i += 32) acc = fmaf(xb[i], Wd[i * 10 + w], acc);
        #pragma unroll
        for (int o = 16; o; o >>= 1) acc += __shfl_xor_sync(0xffffffffu, acc, o);
        if (lane == 0) {
            float h = (acc + bd[w]) * 0.3183098861837907f;  // 1/pi
            float sn, cs;
            sincosf(h, &sn, &cs);
            sh_eih[w] = make_float2(cs, sn);
        }
    }
    __syncthreads();

    // 2. V1[m][j] = sum_k WR1[m][k] * e^{ih_k} * WL1c[k][j]
    if (t < 50) {
        int m = t / 5, j = t % 5;
        float2 v = make_float2(0.f, 0.f);
        #pragma unroll
        for (int k = 0; k < 10; k++)
            v = cadd(v, cmul(sh_WR1[m][k], cmul(sh_eih[k], sh_WL1c[k][j])));
        sh_V[m][j] = v;
    }
    __syncthreads();

    // 3. 252 no-bunching probabilities: 252 threads x single perm (8 warps)
    if (t < N_NB) sh_e1[t] = perm_prob(sh_V, g_tab.nb[t]);
    __syncthreads();

    // 4. phi2[m] = sum_j e1[m + 10j]; then e^{i phi2}
    if (t < 10) {
        float phi = 0.f;
        for (int j2 = t; j2 < N_NB; j2 += 10) phi += sh_e1[j2];
        float sn, cs;
        sincosf(phi, &sn, &cs);
        sh_eih[t] = make_float2(cs, sn);
    }
    __syncthreads();

    // 5. VF[m][j]
    if (t < 50) {
        int m = t / 5, j = t % 5;
        float2 v = make_float2(0.f, 0.f);
        #pragma unroll
        for (int k = 0; k < 10; k++)
            v = cadd(v, cmul(sh_WRF[m][k], cmul(sh_eih[k], sh_WLFc[k][j])));
        sh_V[m][j] = v;
    }
    __syncthreads();

    // 6. 2002 bunched perms, 2-way ILP, fused with probs @ W_out
    //    (EXACT R6 structure: sequential blocks, branchy tail - known-good)
    float acc[10];
    #pragma unroll
    for (int c = 0; c < 10; c++) acc[c] = 0.f;

    {   // pair 0: k = t, t+512
        int kA = t, kB = t + 512;
        float pA, pB;
        perm_prob_dual(sh_V, g_tab.bb[kA], g_tab.bb[kB], pA, pB);
        pA *= g_tab.inv_norm[kA];
        pB *= g_tab.inv_norm[kB];
        const float* wa = Wo + kA * 10;
        const float* wb = Wo + kB * 10;
        #pragma unroll
        for (int c = 0; c < 10; c++) {
            acc[c] = fmaf(pA, wa[c], acc[c]);
            acc[c] = fmaf(pB, wb[c], acc[c]);
        }
    }
    {   // pair 1: k = t+1024, t+1536 (latter valid iff t<466)
        int kA = t + 1024, kB = t + 1536;
        if (kB < N_B) {
            float pA, pB;
            perm_prob_dual(sh_V, g_tab.bb[kA], g_tab.bb[kB], pA, pB);
            pA *= g_tab.inv_norm[kA];
            pB *= g_tab.inv_norm[kB];
            const float* wa = Wo + kA * 10;
            const float* wb = Wo + kB * 10;
            #pragma unroll
            for (int c = 0; c < 10; c++) {
                acc[c] = fmaf(pA, wa[c], acc[c]);
                acc[c] = fmaf(pB, wb[c], acc[c]);
            }
        } else {
            float pA = perm_prob(sh_V, g_tab.bb[kA]) * g_tab.inv_norm[kA];
            const float* wa = Wo + kA * 10;
            #pragma unroll
            for (int c = 0; c < 10; c++) acc[c] = fmaf(pA, wa[c], acc[c]);
        }
    }

    #pragma unroll
    for (int c = 0; c < 10; c++) {
        #pragma unroll
        for (int o = 16; o; o >>= 1) acc[c] += __shfl_xor_sync(0xffffffffu, acc[c], o);
    }
    if (lane == 0) {
        #pragma unroll
        for (int c = 0; c < 10; c++) sh_red[w][c] = acc[c];
    }
    __syncthreads();
    if (t < 10) {
        float v = bo[t];
        #pragma unroll
        for (int ww = 0; ww < 16; ww++) v += sh_red[ww][t];
        out[b * 10 + t] = v;
    }
}

// ---------------------------------------------------------------------------
extern "C" void kernel_launch(void* const* d_in, const int* in_sizes, int n_in,
                              void* d_out, int out_size) {
    const float* x   = (const float*)d_in[0];
    const float* Wd  = (const float*)d_in[1];
    const float* bd  = (const float*)d_in[2];
    const float* pl1 = (const float*)d_in[3];
    const float* pr1 = (const float*)d_in[4];
    const float* plf = (const float*)d_in[5];
    const float* prf = (const float*)d_in[6];
    const float* Wo  = (const float*)d_in[7];
    const float* bo  = (const float*)d_in[8];
    float* out = (float*)d_out;

    int B = in_sizes[0] / 784;

    qc_main<<<B, 512>>>(x, Wd, bd, pl1, pr1, plf, prf, Wo, bo, out);
}